// round 14
// baseline (speedup 1.0000x reference)
#include <cuda_runtime.h>
#include <cuda_bf16.h>
#include <cuda_fp16.h>
#include <cstdint>
#include <math.h>

// ---------------------------------------------------------------------------
// BayesianLinear, R14: fp16-accumulate HMMA probe.
//   out = x @ (mu + exp(ls)*eps)^T + bias
//   unc = sqrt(x^2 @ (exp(ls)^2)^T + bias_sigma^2)
// Fast path (uniform ls): single fp16 product; MMAs accumulate in f16 within
// each BK=64 chunk, promoted to persistent fp32 accumulators per chunk.
// Tests whether the legacy tensor path is MAC-bound (f16-accum = 2x) or
// dispatch-bound (neutral). Calibrated extra error ~3.5e-4 -> total ~5e-4.
// Slow path (non-uniform ls): R10 bf16-split double GEMM, verbatim.
// ---------------------------------------------------------------------------

#define B_DIM   4096
#define IN_DIM  2048
#define OUT_DIM 2048

#define BM 128
#define BN 64

// Fast path: BK=64, rows of 128B.
#define FBK     64
#define FNCHUNK (IN_DIM / FBK)    // 32
#define FT_X    0                 // 128 x 64 fp16 = 16384
#define FT_W    16384             // 64 x 64 fp16 = 8192
#define F_STAGE 24576

// Slow path (R10): BK=32, rows of 64B.
#define BK 32
#define NCHUNK (IN_DIM / BK)      // 64
#define ST_XH   0
#define ST_XL   8192
#define ST_X2   16384
#define ST_WH   24576
#define ST_WL   28672
#define ST_S2H  32768
#define ST_S2L  36864
#define STAGE_BYTES 40960
#define NSTAGE  3
#define SMEM_DYN (NSTAGE * STAGE_BYTES)   // 122880 (covers both paths)

// ---- scratch (allocation-free: __device__ globals) ------------------------
static __device__ __align__(16) __half        g_x16[B_DIM  * IN_DIM];
static __device__ __align__(16) __half        g_w16[OUT_DIM * IN_DIM];
static __device__ __align__(16) __nv_bfloat16 g_xh [B_DIM  * IN_DIM];
static __device__ __align__(16) __nv_bfloat16 g_xl [B_DIM  * IN_DIM];
static __device__ __align__(16) __nv_bfloat16 g_x2 [B_DIM  * IN_DIM];
static __device__ __align__(16) __nv_bfloat16 g_wh [OUT_DIM * IN_DIM];
static __device__ __align__(16) __nv_bfloat16 g_wl [OUT_DIM * IN_DIM];
static __device__ __align__(16) __nv_bfloat16 g_s2h[OUT_DIM * IN_DIM];
static __device__ __align__(16) __nv_bfloat16 g_s2l[OUT_DIM * IN_DIM];
static __device__ int   g_uniform;
static __device__ float g_s2c;
static __device__ float g_rowsum[B_DIM];

// ---- PTX helpers ----------------------------------------------------------
__device__ __forceinline__ uint32_t smem_u32(const void* p) {
    uint32_t a;
    asm("{ .reg .u64 t; cvta.to.shared.u64 t, %1; cvt.u32.u64 %0, t; }"
        : "=r"(a) : "l"(p));
    return a;
}
__device__ __forceinline__ void cp16(uint32_t dst, const void* src) {
    asm volatile("cp.async.cg.shared.global [%0], [%1], 16;"
                 :: "r"(dst), "l"(__cvta_generic_to_global(src)) : "memory");
}
#define CP_COMMIT() asm volatile("cp.async.commit_group;" ::: "memory")
#define CP_WAIT1()  asm volatile("cp.async.wait_group 1;" ::: "memory")

__device__ __forceinline__ void ldsm_x4(uint32_t* r, uint32_t addr) {
    asm volatile("ldmatrix.sync.aligned.m8n8.x4.shared.b16 {%0,%1,%2,%3}, [%4];"
                 : "=r"(r[0]), "=r"(r[1]), "=r"(r[2]), "=r"(r[3]) : "r"(addr));
}
// f16-accumulate form: d/c are 2 regs = 4 halves, layout pairs with f32 case.
__device__ __forceinline__ void mma_f16acc(uint32_t* d, const uint32_t* a,
                                           const uint32_t* b) {
    asm volatile(
        "mma.sync.aligned.m16n8k16.row.col.f16.f16.f16.f16 "
        "{%0,%1}, {%2,%3,%4,%5}, {%6,%7}, {%0,%1};"
        : "+r"(d[0]), "+r"(d[1])
        : "r"(a[0]), "r"(a[1]), "r"(a[2]), "r"(a[3]), "r"(b[0]), "r"(b[1]));
}
__device__ __forceinline__ void mma_bf16(float* d, const uint32_t* a,
                                         const uint32_t* b) {
    asm volatile(
        "mma.sync.aligned.m16n8k16.row.col.f32.bf16.bf16.f32 "
        "{%0,%1,%2,%3}, {%4,%5,%6,%7}, {%8,%9}, {%0,%1,%2,%3};"
        : "+f"(d[0]), "+f"(d[1]), "+f"(d[2]), "+f"(d[3])
        : "r"(a[0]), "r"(a[1]), "r"(a[2]), "r"(a[3]), "r"(b[0]), "r"(b[1]));
}
__device__ __forceinline__ uint32_t pack2(__nv_bfloat16 a, __nv_bfloat16 b) {
    __nv_bfloat162 t(a, b);
    return *reinterpret_cast<uint32_t*>(&t);
}
__device__ __forceinline__ uint32_t packh2(float a, float b) {
    __half2 t = __floats2half2_rn(a, b);
    return *reinterpret_cast<uint32_t*>(&t);
}
// swizzle: 64B rows (4 x 16B chunks) -- slow path tiles
__device__ __forceinline__ uint32_t swz64(int row, int c) {
    return (uint32_t)(row * 64 + ((c ^ ((row >> 1) & 3)) << 4));
}
// swizzle: 128B rows (8 x 16B chunks) -- fast path tiles
__device__ __forceinline__ uint32_t swz128(int row, int c) {
    return (uint32_t)(row * 128 + ((c ^ (row & 7)) << 4));
}

// ---------------------------------------------------------------------------
__global__ void flag_init(const float* __restrict__ ls) {
    g_uniform = 1;
    g_s2c = expf(2.0f * ls[0]);
}
// uniformity detector: runs BEFORE prep so prep can skip slow-path arrays.
__global__ void __launch_bounds__(256) detect_ls(const float4* __restrict__ ls) {
    int i = blockIdx.x * 256 + threadIdx.x;
    float r0 = reinterpret_cast<const float*>(ls)[0];
    float4 l = ls[i];
    if (l.x != r0 || l.y != r0 || l.z != r0 || l.w != r0) g_uniform = 0;
}

// ---------------------------------------------------------------------------
// prep_w: uniform -> fp16(w) only. non-uniform -> full bf16 splits (R10).
// ---------------------------------------------------------------------------
__global__ void __launch_bounds__(256) prep_w(const float4* __restrict__ mu,
                                              const float4* __restrict__ ls,
                                              const float4* __restrict__ ep) {
    int i = blockIdx.x * 256 + threadIdx.x;
    float4 m = mu[i], l = ls[i], e = ep[i];
    float s0 = __expf(l.x), s1 = __expf(l.y), s2 = __expf(l.z), s3 = __expf(l.w);
    float w0 = m.x + s0 * e.x, w1 = m.y + s1 * e.y;
    float w2 = m.z + s2 * e.z, w3 = m.w + s3 * e.w;

    if (g_uniform) {
        reinterpret_cast<uint2*>(g_w16)[i] =
            make_uint2(packh2(w0, w1), packh2(w2, w3));
        return;
    }
    __nv_bfloat16 h0 = __float2bfloat16(w0), h1 = __float2bfloat16(w1);
    __nv_bfloat16 h2 = __float2bfloat16(w2), h3 = __float2bfloat16(w3);
    float lo0 = w0 - __bfloat162float(h0), lo1 = w1 - __bfloat162float(h1);
    float lo2 = w2 - __bfloat162float(h2), lo3 = w3 - __bfloat162float(h3);

    float q0 = s0 * s0, q1 = s1 * s1, q2 = s2 * s2, q3 = s3 * s3;
    __nv_bfloat16 a0 = __float2bfloat16(q0), a1 = __float2bfloat16(q1);
    __nv_bfloat16 a2 = __float2bfloat16(q2), a3 = __float2bfloat16(q3);

    reinterpret_cast<uint2*>(g_wh )[i] = make_uint2(pack2(h0, h1), pack2(h2, h3));
    reinterpret_cast<uint2*>(g_wl )[i] = make_uint2(
        pack2(__float2bfloat16(lo0), __float2bfloat16(lo1)),
        pack2(__float2bfloat16(lo2), __float2bfloat16(lo3)));
    reinterpret_cast<uint2*>(g_s2h)[i] = make_uint2(pack2(a0, a1), pack2(a2, a3));
    reinterpret_cast<uint2*>(g_s2l)[i] = make_uint2(
        pack2(__float2bfloat16(q0 - __bfloat162float(a0)),
              __float2bfloat16(q1 - __bfloat162float(a1))),
        pack2(__float2bfloat16(q2 - __bfloat162float(a2)),
              __float2bfloat16(q3 - __bfloat162float(a3))));
}

// ---------------------------------------------------------------------------
// prep_x: one warp per row. uniform -> fp16(x) + fp32 rowsum(x^2).
// non-uniform -> bf16 hi/lo + x^2 (R10 operands).
// ---------------------------------------------------------------------------
__global__ void __launch_bounds__(256) prep_x(const float4* __restrict__ x) {
    int wrow = blockIdx.x * 8 + (threadIdx.x >> 5);
    int lane = threadIdx.x & 31;
    int uni  = g_uniform;
    const float4* row = x + (size_t)wrow * (IN_DIM / 4);
    size_t gbase = (size_t)wrow * (IN_DIM / 4);
    float s = 0.f;
#pragma unroll
    for (int k = 0; k < 16; ++k) {
        int i = lane + k * 32;
        float4 v = row[i];
        size_t gi = gbase + i;
        if (uni) {
            s += v.x * v.x + v.y * v.y + v.z * v.z + v.w * v.w;
            reinterpret_cast<uint2*>(g_x16)[gi] =
                make_uint2(packh2(v.x, v.y), packh2(v.z, v.w));
        } else {
            __nv_bfloat16 h0 = __float2bfloat16(v.x), h1 = __float2bfloat16(v.y);
            __nv_bfloat16 h2 = __float2bfloat16(v.z), h3 = __float2bfloat16(v.w);
            reinterpret_cast<uint2*>(g_xh)[gi] = make_uint2(
                pack2(h0, h1), pack2(h2, h3));
            reinterpret_cast<uint2*>(g_xl)[gi] = make_uint2(
                pack2(__float2bfloat16(v.x - __bfloat162float(h0)),
                      __float2bfloat16(v.y - __bfloat162float(h1))),
                pack2(__float2bfloat16(v.z - __bfloat162float(h2)),
                      __float2bfloat16(v.w - __bfloat162float(h3))));
            reinterpret_cast<uint2*>(g_x2)[gi] = make_uint2(
                pack2(__float2bfloat16(v.x * v.x), __float2bfloat16(v.y * v.y)),
                pack2(__float2bfloat16(v.z * v.z), __float2bfloat16(v.w * v.w)));
        }
    }
    if (uni) {
#pragma unroll
        for (int o = 16; o > 0; o >>= 1)
            s += __shfl_xor_sync(0xFFFFFFFFu, s, o);
        if (lane == 0) g_rowsum[wrow] = s;
    }
}

// ---------------------------------------------------------------------------
// Main kernel. CTA = 128(M) x 64(N), 512 threads / 16 warps.
// Fast path: fp16 product with f16-accum + per-chunk fp32 promotion.
// Slow path: R10 verbatim (warps 0-7 out / 8-15 var), BK=32.
// ---------------------------------------------------------------------------
__global__ void __launch_bounds__(512, 1) bl_main(
    const float* __restrict__ bias_mu,
    const float* __restrict__ bias_ls,
    const float* __restrict__ eps_b,
    float* __restrict__ out,
    float* __restrict__ unc)
{
    extern __shared__ __align__(128) char dsm[];
    __shared__ float sbias[BN], sbs2[BN], rs_s[BM];

    const int tid = threadIdx.x;
    const int wid = tid >> 5;
    const int lid = tid & 31;
    const int bm  = blockIdx.y * BM;
    const int bn  = blockIdx.x * BN;
    const int uni = g_uniform;

    if (tid < BN) {
        int n = bn + tid;
        float s = __expf(bias_ls[n]);
        sbias[tid] = bias_mu[n] + s * eps_b[n];
        sbs2[tid]  = s * s;
    }
    if (uni && tid >= 256 && tid < 256 + BM)
        rs_s[tid - 256] = g_rowsum[bm + tid - 256];

    const int q  = lid >> 3;       // ldmatrix quadrant
    const int r  = lid & 7;
    const int g2 = lid >> 2;
    const int tc = lid & 3;

    if (uni) {
        // =================== FAST PATH (fp16, f16-accum probe) =============
        const int xrA = tid >> 3, xc = tid & 7;     // rows 0..63
        const int xrB = 64 + xrA;                   // rows 64..127
        const uint32_t sxA = FT_X + swz128(xrA, xc);
        const uint32_t sxB = FT_X + swz128(xrB, xc);
        const uint32_t sw  = FT_W + swz128(xrA, xc);
        const __half* pxA = g_x16 + (size_t)(bm + xrA) * IN_DIM + xc * 8;
        const __half* pxB = g_x16 + (size_t)(bm + xrB) * IN_DIM + xc * 8;
        const __half* pw  = g_w16 + (size_t)(bn + xrA) * IN_DIM + xc * 8;

        auto fast_load = [&](int slot, int kt) {
            uint32_t sb = smem_u32(dsm) + slot * F_STAGE;
            cp16(sb + sxA, pxA + kt);
            cp16(sb + sxB, pxB + kt);
            cp16(sb + sw,  pw  + kt);
        };
        fast_load(0, 0);      CP_COMMIT();
        fast_load(1, FBK);    CP_COMMIT();

        float acc[2][2][4];
#pragma unroll
        for (int i = 0; i < 2; ++i)
#pragma unroll
            for (int j = 0; j < 2; ++j)
#pragma unroll
                for (int e = 0; e < 4; ++e) acc[i][j][e] = 0.f;

        const int wm = (wid >> 2) * 32;   // 0/32/64/96
        const int wn = (wid & 3) * 16;    // 0/16/32/48

        for (int c = 0; c < FNCHUNK; ++c) {
            CP_WAIT1();
            __syncthreads();
            if (c + 2 < FNCHUNK) fast_load((c + 2) % NSTAGE, (c + 2) * FBK);
            CP_COMMIT();

            char* st = dsm + (c % NSTAGE) * F_STAGE;
            const uint32_t Xb = smem_u32(st + FT_X);
            const uint32_t Wb = smem_u32(st + FT_W);

            // per-chunk f16 accumulators (zeroed each chunk)
            uint32_t h16[2][2][2];
#pragma unroll
            for (int i = 0; i < 2; ++i)
#pragma unroll
                for (int j = 0; j < 2; ++j) { h16[i][j][0] = 0u; h16[i][j][1] = 0u; }

#pragma unroll
            for (int ks = 0; ks < 4; ++ks) {
                uint32_t a[2][4], b[4];
#pragma unroll
                for (int mt = 0; mt < 2; ++mt) {
                    int row = wm + mt * 16 + ((q & 1) << 3) + r;
                    ldsm_x4(a[mt], Xb + swz128(row, ks * 2 + (q >> 1)));
                }
                {
                    int row = wn + ((q >> 1) << 3) + r;
                    ldsm_x4(b, Wb + swz128(row, ks * 2 + (q & 1)));
                }
#pragma unroll
                for (int mt = 0; mt < 2; ++mt)
#pragma unroll
                    for (int h = 0; h < 2; ++h)
                        mma_f16acc(h16[mt][h], a[mt], &b[h * 2]);
            }
            // promote chunk partials to fp32 accumulators
#pragma unroll
            for (int mt = 0; mt < 2; ++mt)
#pragma unroll
                for (int h = 0; h < 2; ++h) {
                    float2 lo = __half22float2(
                        *reinterpret_cast<__half2*>(&h16[mt][h][0]));
                    float2 hi = __half22float2(
                        *reinterpret_cast<__half2*>(&h16[mt][h][1]));
                    acc[mt][h][0] += lo.x;  acc[mt][h][1] += lo.y;
                    acc[mt][h][2] += hi.x;  acc[mt][h][3] += hi.y;
                }
        }

        const float s2c = g_s2c;
#pragma unroll
        for (int mt = 0; mt < 2; ++mt)
#pragma unroll
            for (int nt = 0; nt < 2; ++nt) {
                int ml = wm + mt * 16 + g2;
                int nl = wn + nt * 8 + tc * 2;
                size_t o0 = (size_t)(bm + ml) * OUT_DIM + bn + nl;
                const float* a = acc[mt][nt];
                *reinterpret_cast<float2*>(&out[o0]) =
                    make_float2(a[0] + sbias[nl], a[1] + sbias[nl + 1]);
                *reinterpret_cast<float2*>(&out[o0 + 8 * OUT_DIM]) =
                    make_float2(a[2] + sbias[nl], a[3] + sbias[nl + 1]);
                float vA = s2c * rs_s[ml], vB = s2c * rs_s[ml + 8];
                *reinterpret_cast<float2*>(&unc[o0]) = make_float2(
                    sqrtf(vA + sbs2[nl]), sqrtf(vA + sbs2[nl + 1]));
                *reinterpret_cast<float2*>(&unc[o0 + 8 * OUT_DIM]) = make_float2(
                    sqrtf(vB + sbs2[nl]), sqrtf(vB + sbs2[nl + 1]));
            }
        return;
    }

    // ====================== SLOW PATH: R10 verbatim ========================
    const int arow = tid >> 2, acol = tid & 3;
    const uint32_t aoff = swz64(arow, acol);
    const size_t  agoff = (size_t)arow * IN_DIM + acol * 8;

    const __nv_bfloat16* __restrict__ Asrc[3] = {
        g_xh + (size_t)bm * IN_DIM, g_xl + (size_t)bm * IN_DIM,
        g_x2 + (size_t)bm * IN_DIM };
    const __nv_bfloat16* __restrict__ Bsrc[4] = {
        g_wh + (size_t)bn * IN_DIM, g_wl + (size_t)bn * IN_DIM,
        g_s2h + (size_t)bn * IN_DIM, g_s2l + (size_t)bn * IN_DIM };

    const int bid0 = tid, bid1 = tid + 512;

    auto stage_load = [&](int slot, int kt) {
        char* st = dsm + slot * STAGE_BYTES;
#pragma unroll
        for (int t = 0; t < 3; ++t)
            cp16(smem_u32(st + t * 8192 + aoff), Asrc[t] + agoff + kt);
#pragma unroll
        for (int u = 0; u < 2; ++u) {
            int id  = u ? bid1 : bid0;
            int t   = id >> 8;
            int ch  = id & 255;
            int row = ch >> 2, c = ch & 3;
            cp16(smem_u32(st + ST_WH + t * 4096 + swz64(row, c)),
                 Bsrc[t] + (size_t)row * IN_DIM + kt + c * 8);
        }
    };

    stage_load(0, 0);    CP_COMMIT();
    stage_load(1, BK);   CP_COMMIT();

    float acc[2][4][4];
#pragma unroll
    for (int i = 0; i < 2; ++i)
#pragma unroll
        for (int j = 0; j < 4; ++j)
#pragma unroll
            for (int e = 0; e < 4; ++e) acc[i][j][e] = 0.f;

    const bool isVar = (wid >= 8);
    const int  w     = wid & 7;
    const int  wm    = (w >> 1) * 32;
    const int  wn    = (w & 1) * 32;

    for (int c = 0; c < NCHUNK; ++c) {
        CP_WAIT1();
        __syncthreads();
        if (c + 2 < NCHUNK) stage_load((c + 2) % NSTAGE, (c + 2) * BK);
        CP_COMMIT();

        char* st = dsm + (c % NSTAGE) * STAGE_BYTES;
        const uint32_t a0b = smem_u32(st + (isVar ? ST_X2  : ST_XH));
        const uint32_t a1b = smem_u32(st + ST_XL);
        const uint32_t b0b = smem_u32(st + (isVar ? ST_S2H : ST_WH));
        const uint32_t b1b = smem_u32(st + (isVar ? ST_S2L : ST_WL));

#pragma unroll
        for (int ks = 0; ks < 2; ++ks) {
            uint32_t a0[2][4], a1[2][4];
#pragma unroll
            for (int mt = 0; mt < 2; ++mt) {
                int row = wm + mt * 16 + ((q & 1) << 3) + r;
                int cc  = ks * 2 + (q >> 1);
                uint32_t off = swz64(row, cc);
                ldsm_x4(a0[mt], a0b + off);
                if (!isVar) ldsm_x4(a1[mt], a1b + off);
            }
#pragma unroll
            for (int p = 0; p < 2; ++p) {
                uint32_t b0[4], b1[4];
                int row = wn + p * 16 + ((q >> 1) << 3) + r;
                int cc  = ks * 2 + (q & 1);
                uint32_t off = swz64(row, cc);
                ldsm_x4(b0, b0b + off);
                ldsm_x4(b1, b1b + off);
#pragma unroll
                for (int mt = 0; mt < 2; ++mt)
#pragma unroll
                    for (int h = 0; h < 2; ++h) {
                        float* a = acc[mt][2 * p + h];
                        mma_bf16(a, a0[mt], &b0[h * 2]);
                        mma_bf16(a, a0[mt], &b1[h * 2]);
                        if (!isVar) mma_bf16(a, a1[mt], &b0[h * 2]);
                    }
            }
        }
    }

    float* dst = isVar ? unc : out;
#pragma unroll
    for (int mt = 0; mt < 2; ++mt)
#pragma unroll
        for (int nt = 0; nt < 4; ++nt) {
            int m  = bm + wm + mt * 16 + g2;
            int nl = wn + nt * 8 + tc * 2;
            size_t o0 = (size_t)m * OUT_DIM + bn + nl;
            const float* a = acc[mt][nt];
            float2 v0, v1;
            if (isVar) {
                v0 = make_float2(sqrtf(a[0] + sbs2[nl]), sqrtf(a[1] + sbs2[nl + 1]));
                v1 = make_float2(sqrtf(a[2] + sbs2[nl]), sqrtf(a[3] + sbs2[nl + 1]));
            } else {
                v0 = make_float2(a[0] + sbias[nl], a[1] + sbias[nl + 1]);
                v1 = make_float2(a[2] + sbias[nl], a[3] + sbias[nl + 1]);
            }
            *reinterpret_cast<float2*>(&dst[o0]) = v0;
            *reinterpret_cast<float2*>(&dst[o0 + 8 * OUT_DIM]) = v1;
        }
}

// ---------------------------------------------------------------------------
// kernel_launch — graph-capturable, allocation-free.
// Inputs: x, weight_mu, weight_log_sigma, bias_mu, bias_log_sigma, eps_w, eps_b
// Output: [output | uncertainty] fp32, each 4096x2048.
// ---------------------------------------------------------------------------
extern "C" void kernel_launch(void* const* d_in, const int* in_sizes, int n_in,
                              void* d_out, int out_size)
{
    const float* x   = (const float*)d_in[0];
    const float* wmu = (const float*)d_in[1];
    const float* wls = (const float*)d_in[2];
    const float* bmu = (const float*)d_in[3];
    const float* bls = (const float*)d_in[4];
    const float* ew  = (const float*)d_in[5];
    const float* eb  = (const float*)d_in[6];

    float* out = (float*)d_out;
    float* unc = out + (size_t)B_DIM * OUT_DIM;

    cudaFuncSetAttribute(bl_main, cudaFuncAttributeMaxDynamicSharedMemorySize,
                         SMEM_DYN);

    flag_init<<<1, 1>>>(wls);
    detect_ls<<<(OUT_DIM * IN_DIM / 4) / 256, 256>>>((const float4*)wls);
    prep_w<<<(OUT_DIM * IN_DIM / 4) / 256, 256>>>(
        (const float4*)wmu, (const float4*)wls, (const float4*)ew);
    prep_x<<<B_DIM / 8, 256>>>((const float4*)x);

    dim3 grid(OUT_DIM / BN, B_DIM / BM);   // (32, 32) = 1024 CTAs
    bl_main<<<grid, 512, SMEM_DYN>>>(bmu, bls, eb, out, unc);

    (void)in_sizes; (void)n_in; (void)out_size;
}

// round 17
// speedup vs baseline: 1.0856x; 1.0856x over previous
#include <cuda_runtime.h>
#include <cuda_bf16.h>
#include <cuda_fp16.h>
#include <cstdint>
#include <math.h>

// ---------------------------------------------------------------------------
// BayesianLinear, R15: fp16 single-product HMMA (f32 accum), BK=128,
// detection fused into prep, conditional fixup for the slow path.
//   out = x @ (mu + exp(ls)*eps)^T + bias
//   unc = sqrt(x^2 @ (exp(ls)^2)^T + bias_sigma^2)
// Fast path (uniform ls): out = fp16(x) @ fp16(w)^T (m16n8k16.f32), rel ~2.9e-4;
//   unc from fp32 rowsum (exact). Slow path: R10 bf16-split double GEMM.
// Calibration (R12/R14): mma.sync is DISPATCH-bound at 16cyc/SMSP for every
// dtype/accum combo -> only fewer MMA instructions or less overhead helps.
// ---------------------------------------------------------------------------

#define B_DIM   4096
#define IN_DIM  2048
#define OUT_DIM 2048

#define BM 128
#define BN 64

// Fast path: BK=128 as two 64-k sub-tiles (same 128B-row swizzle as R13).
#define FBK     128
#define FNCHUNK (IN_DIM / FBK)    // 16
#define FT_X    0                 // 2 x (128 x 64 fp16) = 32768
#define FT_W    32768             // 2 x ( 64 x 64 fp16) = 16384
#define F_STAGE 49152

// Slow path (R10): BK=32, rows of 64B.
#define BK 32
#define NCHUNK (IN_DIM / BK)      // 64
#define ST_XH   0
#define ST_XL   8192
#define ST_X2   16384
#define ST_WH   24576
#define ST_WL   28672
#define ST_S2H  32768
#define ST_S2L  36864
#define STAGE_BYTES 40960
#define NSTAGE  3
#define SMEM_DYN (NSTAGE * F_STAGE)   // 147456 >= slow path's 122880

// ---- scratch (allocation-free: __device__ globals) ------------------------
static __device__ __align__(16) __half        g_x16[B_DIM  * IN_DIM];
static __device__ __align__(16) __half        g_w16[OUT_DIM * IN_DIM];
static __device__ __align__(16) __nv_bfloat16 g_xh [B_DIM  * IN_DIM];
static __device__ __align__(16) __nv_bfloat16 g_xl [B_DIM  * IN_DIM];
static __device__ __align__(16) __nv_bfloat16 g_x2 [B_DIM  * IN_DIM];
static __device__ __align__(16) __nv_bfloat16 g_wh [OUT_DIM * IN_DIM];
static __device__ __align__(16) __nv_bfloat16 g_wl [OUT_DIM * IN_DIM];
static __device__ __align__(16) __nv_bfloat16 g_s2h[OUT_DIM * IN_DIM];
static __device__ __align__(16) __nv_bfloat16 g_s2l[OUT_DIM * IN_DIM];
static __device__ int   g_uniform;
static __device__ float g_s2c;
static __device__ float g_rowsum[B_DIM];

// ---- PTX helpers ----------------------------------------------------------
__device__ __forceinline__ uint32_t smem_u32(const void* p) {
    uint32_t a;
    asm("{ .reg .u64 t; cvta.to.shared.u64 t, %1; cvt.u32.u64 %0, t; }"
        : "=r"(a) : "l"(p));
    return a;
}
__device__ __forceinline__ void cp16(uint32_t dst, const void* src) {
    asm volatile("cp.async.cg.shared.global [%0], [%1], 16;"
                 :: "r"(dst), "l"(__cvta_generic_to_global(src)) : "memory");
}
#define CP_COMMIT() asm volatile("cp.async.commit_group;" ::: "memory")
#define CP_WAIT1()  asm volatile("cp.async.wait_group 1;" ::: "memory")

__device__ __forceinline__ void ldsm_x4(uint32_t* r, uint32_t addr) {
    asm volatile("ldmatrix.sync.aligned.m8n8.x4.shared.b16 {%0,%1,%2,%3}, [%4];"
                 : "=r"(r[0]), "=r"(r[1]), "=r"(r[2]), "=r"(r[3]) : "r"(addr));
}
__device__ __forceinline__ void mma_f16(float* d, const uint32_t* a,
                                        const uint32_t* b) {
    asm volatile(
        "mma.sync.aligned.m16n8k16.row.col.f32.f16.f16.f32 "
        "{%0,%1,%2,%3}, {%4,%5,%6,%7}, {%8,%9}, {%0,%1,%2,%3};"
        : "+f"(d[0]), "+f"(d[1]), "+f"(d[2]), "+f"(d[3])
        : "r"(a[0]), "r"(a[1]), "r"(a[2]), "r"(a[3]), "r"(b[0]), "r"(b[1]));
}
__device__ __forceinline__ void mma_bf16(float* d, const uint32_t* a,
                                         const uint32_t* b) {
    asm volatile(
        "mma.sync.aligned.m16n8k16.row.col.f32.bf16.bf16.f32 "
        "{%0,%1,%2,%3}, {%4,%5,%6,%7}, {%8,%9}, {%0,%1,%2,%3};"
        : "+f"(d[0]), "+f"(d[1]), "+f"(d[2]), "+f"(d[3])
        : "r"(a[0]), "r"(a[1]), "r"(a[2]), "r"(a[3]), "r"(b[0]), "r"(b[1]));
}
__device__ __forceinline__ uint32_t pack2(__nv_bfloat16 a, __nv_bfloat16 b) {
    __nv_bfloat162 t(a, b);
    return *reinterpret_cast<uint32_t*>(&t);
}
__device__ __forceinline__ uint32_t packh2(float a, float b) {
    __half2 t = __floats2half2_rn(a, b);
    return *reinterpret_cast<uint32_t*>(&t);
}
// swizzle: 64B rows (slow path tiles)
__device__ __forceinline__ uint32_t swz64(int row, int c) {
    return (uint32_t)(row * 64 + ((c ^ ((row >> 1) & 3)) << 4));
}
// swizzle: 128B rows (fast path sub-tiles)
__device__ __forceinline__ uint32_t swz128(int row, int c) {
    return (uint32_t)(row * 128 + ((c ^ (row & 7)) << 4));
}

// ---------------------------------------------------------------------------
__global__ void flag_init(const float* __restrict__ ls) {
    g_uniform = 1;
    g_s2c = expf(2.0f * ls[0]);
}

// prep_w: ALWAYS writes fp16(w) (valid for both paths) and detects
// non-uniform ls inline (it must read ls anyway to form w).
__global__ void __launch_bounds__(256) prep_w(const float4* __restrict__ mu,
                                              const float4* __restrict__ ls,
                                              const float4* __restrict__ ep) {
    int i = blockIdx.x * 256 + threadIdx.x;
    float4 m = mu[i], l = ls[i], e = ep[i];
    float r0 = reinterpret_cast<const float*>(ls)[0];
    if (l.x != r0 || l.y != r0 || l.z != r0 || l.w != r0) g_uniform = 0;

    float s0 = __expf(l.x), s1 = __expf(l.y), s2 = __expf(l.z), s3 = __expf(l.w);
    float w0 = m.x + s0 * e.x, w1 = m.y + s1 * e.y;
    float w2 = m.z + s2 * e.z, w3 = m.w + s3 * e.w;
    reinterpret_cast<uint2*>(g_w16)[i] =
        make_uint2(packh2(w0, w1), packh2(w2, w3));
}

// prep_x: ALWAYS writes fp16(x) + fp32 rowsum(x^2). One warp per row.
__global__ void __launch_bounds__(256) prep_x(const float4* __restrict__ x) {
    int wrow = blockIdx.x * 8 + (threadIdx.x >> 5);
    int lane = threadIdx.x & 31;
    const float4* row = x + (size_t)wrow * (IN_DIM / 4);
    size_t gbase = (size_t)wrow * (IN_DIM / 4);
    float s = 0.f;
#pragma unroll
    for (int k = 0; k < 16; ++k) {
        int i = lane + k * 32;
        float4 v = row[i];
        s += v.x * v.x + v.y * v.y + v.z * v.z + v.w * v.w;
        reinterpret_cast<uint2*>(g_x16)[gbase + i] =
            make_uint2(packh2(v.x, v.y), packh2(v.z, v.w));
    }
#pragma unroll
    for (int o = 16; o > 0; o >>= 1)
        s += __shfl_xor_sync(0xFFFFFFFFu, s, o);
    if (lane == 0) g_rowsum[wrow] = s;
}

// fixup_w: slow-path bf16 split operands; early-exits when uniform.
// grid-stride: 2 float4 elements per thread, 2048 blocks.
__global__ void __launch_bounds__(256) fixup_w(const float4* __restrict__ mu,
                                               const float4* __restrict__ ls,
                                               const float4* __restrict__ ep) {
    if (g_uniform) return;
    int base = (blockIdx.x * 256 + threadIdx.x) * 2;
#pragma unroll
    for (int u = 0; u < 2; ++u) {
        int i = base + u;
        float4 m = mu[i], l = ls[i], e = ep[i];
        float s0 = __expf(l.x), s1 = __expf(l.y);
        float s2 = __expf(l.z), s3 = __expf(l.w);
        float w0 = m.x + s0 * e.x, w1 = m.y + s1 * e.y;
        float w2 = m.z + s2 * e.z, w3 = m.w + s3 * e.w;

        __nv_bfloat16 h0 = __float2bfloat16(w0), h1 = __float2bfloat16(w1);
        __nv_bfloat16 h2 = __float2bfloat16(w2), h3 = __float2bfloat16(w3);
        float lo0 = w0 - __bfloat162float(h0), lo1 = w1 - __bfloat162float(h1);
        float lo2 = w2 - __bfloat162float(h2), lo3 = w3 - __bfloat162float(h3);

        float q0 = s0 * s0, q1 = s1 * s1, q2 = s2 * s2, q3 = s3 * s3;
        __nv_bfloat16 a0 = __float2bfloat16(q0), a1 = __float2bfloat16(q1);
        __nv_bfloat16 a2 = __float2bfloat16(q2), a3 = __float2bfloat16(q3);

        reinterpret_cast<uint2*>(g_wh )[i] = make_uint2(pack2(h0, h1),
                                                        pack2(h2, h3));
        reinterpret_cast<uint2*>(g_wl )[i] = make_uint2(
            pack2(__float2bfloat16(lo0), __float2bfloat16(lo1)),
            pack2(__float2bfloat16(lo2), __float2bfloat16(lo3)));
        reinterpret_cast<uint2*>(g_s2h)[i] = make_uint2(pack2(a0, a1),
                                                        pack2(a2, a3));
        reinterpret_cast<uint2*>(g_s2l)[i] = make_uint2(
            pack2(__float2bfloat16(q0 - __bfloat162float(a0)),
                  __float2bfloat16(q1 - __bfloat162float(a1))),
            pack2(__float2bfloat16(q2 - __bfloat162float(a2)),
                  __float2bfloat16(q3 - __bfloat162float(a3))));
    }
}

// fixup_x: slow-path x operands; early-exits when uniform.
__global__ void __launch_bounds__(256) fixup_x(const float4* __restrict__ x) {
    if (g_uniform) return;
    int wrow = blockIdx.x * 8 + (threadIdx.x >> 5);
    int lane = threadIdx.x & 31;
    const float4* row = x + (size_t)wrow * (IN_DIM / 4);
    size_t gbase = (size_t)wrow * (IN_DIM / 4);
#pragma unroll
    for (int k = 0; k < 16; ++k) {
        int i = lane + k * 32;
        float4 v = row[i];
        size_t gi = gbase + i;
        __nv_bfloat16 h0 = __float2bfloat16(v.x), h1 = __float2bfloat16(v.y);
        __nv_bfloat16 h2 = __float2bfloat16(v.z), h3 = __float2bfloat16(v.w);
        reinterpret_cast<uint2*>(g_xh)[gi] = make_uint2(pack2(h0, h1),
                                                        pack2(h2, h3));
        reinterpret_cast<uint2*>(g_xl)[gi] = make_uint2(
            pack2(__float2bfloat16(v.x - __bfloat162float(h0)),
                  __float2bfloat16(v.y - __bfloat162float(h1))),
            pack2(__float2bfloat16(v.z - __bfloat162float(h2)),
                  __float2bfloat16(v.w - __bfloat162float(h3))));
        reinterpret_cast<uint2*>(g_x2)[gi] = make_uint2(
            pack2(__float2bfloat16(v.x * v.x), __float2bfloat16(v.y * v.y)),
            pack2(__float2bfloat16(v.z * v.z), __float2bfloat16(v.w * v.w)));
    }
}

// ---------------------------------------------------------------------------
// Main kernel. CTA = 128(M) x 64(N), 512 threads / 16 warps.
// Fast path: fp16 single product, f32 accum, BK=128 (2 sub-tiles), 3 stages.
// Slow path: R10 verbatim (warps 0-7 out / 8-15 var), BK=32.
// ---------------------------------------------------------------------------
__global__ void __launch_bounds__(512, 1) bl_main(
    const float* __restrict__ bias_mu,
    const float* __restrict__ bias_ls,
    const float* __restrict__ eps_b,
    float* __restrict__ out,
    float* __restrict__ unc)
{
    extern __shared__ __align__(128) char dsm[];
    __shared__ float sbias[BN], sbs2[BN], rs_s[BM];

    const int tid = threadIdx.x;
    const int wid = tid >> 5;
    const int lid = tid & 31;
    const int bm  = blockIdx.y * BM;
    const int bn  = blockIdx.x * BN;
    const int uni = g_uniform;

    if (tid < BN) {
        int n = bn + tid;
        float s = __expf(bias_ls[n]);
        sbias[tid] = bias_mu[n] + s * eps_b[n];
        sbs2[tid]  = s * s;
    }
    if (uni && tid >= 256 && tid < 256 + BM)
        rs_s[tid - 256] = g_rowsum[bm + tid - 256];

    const int q  = lid >> 3;       // ldmatrix quadrant
    const int r  = lid & 7;
    const int g2 = lid >> 2;
    const int tc = lid & 3;

    if (uni) {
        // =================== FAST PATH (fp16, f32 accum, BK=128) ===========
        const int xrA = tid >> 3, xc = tid & 7;     // rows 0..63
        const int xrB = 64 + xrA;                   // rows 64..127
        const uint32_t swA = swz128(xrA, xc);
        const uint32_t swB = swz128(xrB, xc);
        const __half* pxA = g_x16 + (size_t)(bm + xrA) * IN_DIM + xc * 8;
        const __half* pxB = g_x16 + (size_t)(bm + xrB) * IN_DIM + xc * 8;
        const __half* pw  = g_w16 + (size_t)(bn + xrA) * IN_DIM + xc * 8;

        auto fast_load = [&](int slot, int kt) {
            uint32_t sb = smem_u32(dsm) + slot * F_STAGE;
#pragma unroll
            for (int h = 0; h < 2; ++h) {
                cp16(sb + FT_X + h * 16384 + swA, pxA + kt + h * 64);
                cp16(sb + FT_X + h * 16384 + swB, pxB + kt + h * 64);
                cp16(sb + FT_W + h * 8192  + swA, pw  + kt + h * 64);
            }
        };
        fast_load(0, 0);      CP_COMMIT();
        fast_load(1, FBK);    CP_COMMIT();

        float acc[2][2][4];
#pragma unroll
        for (int i = 0; i < 2; ++i)
#pragma unroll
            for (int j = 0; j < 2; ++j)
#pragma unroll
                for (int e = 0; e < 4; ++e) acc[i][j][e] = 0.f;

        const int wm = (wid >> 2) * 32;   // 0/32/64/96
        const int wn = (wid & 3) * 16;    // 0/16/32/48

        for (int c = 0; c < FNCHUNK; ++c) {
            CP_WAIT1();
            __syncthreads();
            if (c + 2 < FNCHUNK) fast_load((c + 2) % NSTAGE, (c + 2) * FBK);
            CP_COMMIT();

            char* st = dsm + (c % NSTAGE) * F_STAGE;
#pragma unroll
            for (int h2v = 0; h2v < 2; ++h2v) {     // 64-k sub-tiles
                const uint32_t Xb = smem_u32(st + FT_X + h2v * 16384);
                const uint32_t Wb = smem_u32(st + FT_W + h2v * 8192);
#pragma unroll
                for (int ks = 0; ks < 4; ++ks) {
                    uint32_t a[2][4], b[4];
#pragma unroll
                    for (int mt = 0; mt < 2; ++mt) {
                        int row = wm + mt * 16 + ((q & 1) << 3) + r;
                        ldsm_x4(a[mt], Xb + swz128(row, ks * 2 + (q >> 1)));
                    }
                    {
                        int row = wn + ((q >> 1) << 3) + r;
                        ldsm_x4(b, Wb + swz128(row, ks * 2 + (q & 1)));
                    }
#pragma unroll
                    for (int mt = 0; mt < 2; ++mt)
#pragma unroll
                        for (int h = 0; h < 2; ++h)
                            mma_f16(acc[mt][h], a[mt], &b[h * 2]);
                }
            }
        }

        const float s2c = g_s2c;
#pragma unroll
        for (int mt = 0; mt < 2; ++mt)
#pragma unroll
            for (int nt = 0; nt < 2; ++nt) {
                int ml = wm + mt * 16 + g2;
                int nl = wn + nt * 8 + tc * 2;
                size_t o0 = (size_t)(bm + ml) * OUT_DIM + bn + nl;
                const float* a = acc[mt][nt];
                *reinterpret_cast<float2*>(&out[o0]) =
                    make_float2(a[0] + sbias[nl], a[1] + sbias[nl + 1]);
                *reinterpret_cast<float2*>(&out[o0 + 8 * OUT_DIM]) =
                    make_float2(a[2] + sbias[nl], a[3] + sbias[nl + 1]);
                float vA = s2c * rs_s[ml], vB = s2c * rs_s[ml + 8];
                *reinterpret_cast<float2*>(&unc[o0]) = make_float2(
                    sqrtf(vA + sbs2[nl]), sqrtf(vA + sbs2[nl + 1]));
                *reinterpret_cast<float2*>(&unc[o0 + 8 * OUT_DIM]) = make_float2(
                    sqrtf(vB + sbs2[nl]), sqrtf(vB + sbs2[nl + 1]));
            }
        return;
    }

    // ====================== SLOW PATH: R10 verbatim ========================
    const int arow = tid >> 2, acol = tid & 3;
    const uint32_t aoff = swz64(arow, acol);
    const size_t  agoff = (size_t)arow * IN_DIM + acol * 8;

    const __nv_bfloat16* __restrict__ Asrc[3] = {
        g_xh + (size_t)bm * IN_DIM, g_xl + (size_t)bm * IN_DIM,
        g_x2 + (size_t)bm * IN_DIM };
    const __nv_bfloat16* __restrict__ Bsrc[4] = {
        g_wh + (size_t)bn * IN_DIM, g_wl + (size_t)bn * IN_DIM,
        g_s2h + (size_t)bn * IN_DIM, g_s2l + (size_t)bn * IN_DIM };

    const int bid0 = tid, bid1 = tid + 512;

    auto stage_load = [&](int slot, int kt) {
        char* st = dsm + slot * STAGE_BYTES;
#pragma unroll
        for (int t = 0; t < 3; ++t)
            cp16(smem_u32(st + t * 8192 + aoff), Asrc[t] + agoff + kt);
#pragma unroll
        for (int u = 0; u < 2; ++u) {
            int id  = u ? bid1 : bid0;
            int t   = id >> 8;
            int ch  = id & 255;
            int row = ch >> 2, c = ch & 3;
            cp16(smem_u32(st + ST_WH + t * 4096 + swz64(row, c)),
                 Bsrc[t] + (size_t)row * IN_DIM + kt + c * 8);
        }
    };

    stage_load(0, 0);    CP_COMMIT();
    stage_load(1, BK);   CP_COMMIT();

    float acc[2][4][4];
#pragma unroll
    for (int i = 0; i < 2; ++i)
#pragma unroll
        for (int j = 0; j < 4; ++j)
#pragma unroll
            for (int e = 0; e < 4; ++e) acc[i][j][e] = 0.f;

    const bool isVar = (wid >= 8);
    const int  w     = wid & 7;
    const int  wm    = (w >> 1) * 32;
    const int  wn    = (w & 1) * 32;

    for (int c = 0; c < NCHUNK; ++c) {
        CP_WAIT1();
        __syncthreads();
        if (c + 2 < NCHUNK) stage_load((c + 2) % NSTAGE, (c + 2) * BK);
        CP_COMMIT();

        char* st = dsm + (c % NSTAGE) * STAGE_BYTES;
        const uint32_t a0b = smem_u32(st + (isVar ? ST_X2  : ST_XH));
        const uint32_t a1b = smem_u32(st + ST_XL);
        const uint32_t b0b = smem_u32(st + (isVar ? ST_S2H : ST_WH));
        const uint32_t b1b = smem_u32(st + (isVar ? ST_S2L : ST_WL));

#pragma unroll
        for (int ks = 0; ks < 2; ++ks) {
            uint32_t a0[2][4], a1[2][4];
#pragma unroll
            for (int mt = 0; mt < 2; ++mt) {
                int row = wm + mt * 16 + ((q & 1) << 3) + r;
                int cc  = ks * 2 + (q >> 1);
                uint32_t off = swz64(row, cc);
                ldsm_x4(a0[mt], a0b + off);
                if (!isVar) ldsm_x4(a1[mt], a1b + off);
            }
#pragma unroll
            for (int p = 0; p < 2; ++p) {
                uint32_t b0[4], b1[4];
                int row = wn + p * 16 + ((q >> 1) << 3) + r;
                int cc  = ks * 2 + (q & 1);
                uint32_t off = swz64(row, cc);
                ldsm_x4(b0, b0b + off);
                ldsm_x4(b1, b1b + off);
#pragma unroll
                for (int mt = 0; mt < 2; ++mt)
#pragma unroll
                    for (int h = 0; h < 2; ++h) {
                        float* a = acc[mt][2 * p + h];
                        mma_bf16(a, a0[mt], &b0[h * 2]);
                        mma_bf16(a, a0[mt], &b1[h * 2]);
                        if (!isVar) mma_bf16(a, a1[mt], &b0[h * 2]);
                    }
            }
        }
    }

    float* dst = isVar ? unc : out;
#pragma unroll
    for (int mt = 0; mt < 2; ++mt)
#pragma unroll
        for (int nt = 0; nt < 4; ++nt) {
            int m  = bm + wm + mt * 16 + g2;
            int nl = wn + nt * 8 + tc * 2;
            size_t o0 = (size_t)m * OUT_DIM + bn + nl;
            const float* a = acc[mt][nt];
            float2 v0, v1;
            if (isVar) {
                v0 = make_float2(sqrtf(a[0] + sbs2[nl]), sqrtf(a[1] + sbs2[nl + 1]));
                v1 = make_float2(sqrtf(a[2] + sbs2[nl]), sqrtf(a[3] + sbs2[nl + 1]));
            } else {
                v0 = make_float2(a[0] + sbias[nl], a[1] + sbias[nl + 1]);
                v1 = make_float2(a[2] + sbias[nl], a[3] + sbias[nl + 1]);
            }
            *reinterpret_cast<float2*>(&dst[o0]) = v0;
            *reinterpret_cast<float2*>(&dst[o0 + 8 * OUT_DIM]) = v1;
        }
}

// ---------------------------------------------------------------------------
// kernel_launch — graph-capturable, allocation-free.
// Inputs: x, weight_mu, weight_log_sigma, bias_mu, bias_log_sigma, eps_w, eps_b
// Output: [output | uncertainty] fp32, each 4096x2048.
// ---------------------------------------------------------------------------
extern "C" void kernel_launch(void* const* d_in, const int* in_sizes, int n_in,
                              void* d_out, int out_size)
{
    const float* x   = (const float*)d_in[0];
    const float* wmu = (const float*)d_in[1];
    const float* wls = (const float*)d_in[2];
    const float* bmu = (const float*)d_in[3];
    const float* bls = (const float*)d_in[4];
    const float* ew  = (const float*)d_in[5];
    const float* eb  = (const float*)d_in[6];

    float* out = (float*)d_out;
    float* unc = out + (size_t)B_DIM * OUT_DIM;

    cudaFuncSetAttribute(bl_main, cudaFuncAttributeMaxDynamicSharedMemorySize,
                         SMEM_DYN);

    flag_init<<<1, 1>>>(wls);
    prep_w<<<(OUT_DIM * IN_DIM / 4) / 256, 256>>>(
        (const float4*)wmu, (const float4*)wls, (const float4*)ew);
    prep_x<<<B_DIM / 8, 256>>>((const float4*)x);
    fixup_w<<<(OUT_DIM * IN_DIM / 4) / 512, 256>>>(
        (const float4*)wmu, (const float4*)wls, (const float4*)ew);
    fixup_x<<<B_DIM / 8, 256>>>((const float4*)x);

    dim3 grid(OUT_DIM / BN, B_DIM / BM);   // (32, 32) = 1024 CTAs
    bl_main<<<grid, 512, SMEM_DYN>>>(bmu, bls, eb, out, unc);

    (void)in_sizes; (void)n_in; (void)out_size;
}